// round 4
// baseline (speedup 1.0000x reference)
#include <cuda_runtime.h>

#define N_FFT   1024
#define LOG2N   10
#define THREADS 256   // 2 butterflies per thread per stage (512 butterflies total)

__global__ void __launch_bounds__(THREADS) ifft1024_kernel(
    const float* __restrict__ re_in,
    const float* __restrict__ im_in,
    float* __restrict__ out,
    long long half_out)
{
    // Ping-pong smem buffers: 4 * 1024 * 4B = 16 KB
    __shared__ float sAre[N_FFT], sAim[N_FFT], sBre[N_FFT], sBim[N_FFT];

    const int tid = threadIdx.x;
    const long long row = blockIdx.x;
    const long long base = row * (long long)N_FFT;

    // Coalesced float4 load of the whole row into buffer A
    reinterpret_cast<float4*>(sAre)[tid] =
        reinterpret_cast<const float4*>(re_in + base)[tid];
    reinterpret_cast<float4*>(sAim)[tid] =
        reinterpret_cast<const float4*>(im_in + base)[tid];
    __syncthreads();

    float* sre = sAre; float* sim = sAim;   // source
    float* dre = sBre; float* dim_ = sBim;  // destination

    // Stockham self-sorting radix-2 FFT, inverse sign (+), natural-order output.
    #pragma unroll
    for (int stage = 0; stage < LOG2N; ++stage) {
        const int p = 1 << stage;
        #pragma unroll
        for (int b = 0; b < 2; ++b) {
            const int gid = tid + b * THREADS;      // 0..511
            const int k = gid & (p - 1);
            const float ur = sre[gid];
            const float ui = sim[gid];
            const float vr = sre[gid + (N_FFT / 2)];
            const float vi = sim[gid + (N_FFT / 2)];
            // inverse FFT twiddle: w = exp(+i * pi * k / p)
            const float ang = 3.14159265358979f * (float)k / (float)p;
            float s, c;
            __sincosf(ang, &s, &c);
            const float tr = vr * c - vi * s;
            const float ti = vr * s + vi * c;
            const int j = ((gid - k) << 1) + k;
            dre[j]      = ur + tr;
            dim_[j]     = ui + ti;
            dre[j + p]  = ur - tr;
            dim_[j + p] = ui - ti;
        }
        __syncthreads();
        float* t;
        t = sre; sre = dre; dre = t;
        t = sim; sim = dim_; dim_ = t;
    }
    // After 10 stages (even number of swaps), result is back in sAre/sAim == sre/sim.

    const float scale = 1.0f / (float)N_FFT;  // ifft normalization (1/128 * 1/8)
    float4 r = reinterpret_cast<float4*>(sre)[tid];
    float4 i = reinterpret_cast<float4*>(sim)[tid];
    r.x *= scale; r.y *= scale; r.z *= scale; r.w *= scale;
    i.x *= scale; i.y *= scale; i.z *= scale; i.w *= scale;
    reinterpret_cast<float4*>(out + base)[tid] = r;
    reinterpret_cast<float4*>(out + half_out + base)[tid] = i;
}

extern "C" void kernel_launch(void* const* d_in, const int* in_sizes, int n_in,
                              void* d_out, int out_size) {
    const float* re = (const float*)d_in[0];
    const float* im = (const float*)d_in[1];
    float* out = (float*)d_out;

    const int n_elems = in_sizes[0];                 // 8*4096*1024 = 33554432
    const int rows = n_elems / N_FFT;                // 32768
    const long long half = (long long)out_size / 2;  // re | im split in d_out

    ifft1024_kernel<<<rows, THREADS>>>(re, im, out, half);
}

// round 6
// speedup vs baseline: 1.6331x; 1.6331x over previous
#include <cuda_runtime.h>

#define N_FFT   1024
#define THREADS 256
#define SMEM_N  (N_FFT + N_FFT / 32)   // padded: a -> a + (a>>5)

__device__ __forceinline__ int padi(int a) { return a + (a >> 5); }

__global__ void __launch_bounds__(THREADS) ifft1024_r4_kernel(
    const float* __restrict__ re_in,
    const float* __restrict__ im_in,
    float* __restrict__ out,
    long long half_out)
{
    __shared__ float sre[SMEM_N];
    __shared__ float sim[SMEM_N];

    const int tid = threadIdx.x;
    const long long base = (long long)blockIdx.x * N_FFT;

    // Each thread holds 4 complex points in registers (stride-256 layout).
    float ur[4], ui[4];
    #pragma unroll
    for (int m = 0; m < 4; ++m) {
        ur[m] = re_in[base + tid + 256 * m];   // coalesced
        ui[m] = im_in[base + tid + 256 * m];
    }

    const float TWO_PI = 6.28318530717958647692f;
    const float scale  = 1.0f / (float)N_FFT;

    // 5 radix-4 Stockham passes, p = 1,4,16,64,256. Inverse sign (+i).
    #pragma unroll
    for (int pass = 0; pass < 5; ++pass) {
        const int p = 1 << (2 * pass);
        const int k = tid & (p - 1);

        // w = exp(+2*pi*i * k / (4p));  t_m = u_m * w^m
        float c1, s1;
        __sincosf(TWO_PI * (float)k / (float)(4 * p), &s1, &c1);
        const float c2 = c1 * c1 - s1 * s1, s2 = 2.0f * c1 * s1;
        const float c3 = c2 * c1 - s2 * s1, s3 = c2 * s1 + s2 * c1;

        const float t0r = ur[0],                    t0i = ui[0];
        const float t1r = ur[1] * c1 - ui[1] * s1,  t1i = ur[1] * s1 + ui[1] * c1;
        const float t2r = ur[2] * c2 - ui[2] * s2,  t2i = ur[2] * s2 + ui[2] * c2;
        const float t3r = ur[3] * c3 - ui[3] * s3,  t3i = ur[3] * s3 + ui[3] * c3;

        // Radix-4 inverse DFT: y_q = sum_m t_m * exp(+2*pi*i*q*m/4)
        const float a0r = t0r + t2r, a0i = t0i + t2i;
        const float a1r = t0r - t2r, a1i = t0i - t2i;
        const float a2r = t1r + t3r, a2i = t1i + t3i;
        const float a3r = t1r - t3r, a3i = t1i - t3i;

        const float y0r = a0r + a2r, y0i = a0i + a2i;   // q=0
        const float y2r = a0r - a2r, y2i = a0i - a2i;   // q=2
        const float y1r = a1r - a3i, y1i = a1i + a3r;   // q=1: a1 + i*a3
        const float y3r = a1r + a3i, y3i = a1i - a3r;   // q=3: a1 - i*a3

        const int j = ((tid - k) << 2) + k;

        if (pass < 4) {
            if (pass > 0) __syncthreads();   // prior reads complete before overwrite
            sre[padi(j)]         = y0r;  sim[padi(j)]         = y0i;
            sre[padi(j + p)]     = y1r;  sim[padi(j + p)]     = y1i;
            sre[padi(j + 2 * p)] = y2r;  sim[padi(j + 2 * p)] = y2i;
            sre[padi(j + 3 * p)] = y3r;  sim[padi(j + 3 * p)] = y3i;
            __syncthreads();
            #pragma unroll
            for (int m = 0; m < 4; ++m) {
                ur[m] = sre[padi(tid + 256 * m)];
                ui[m] = sim[padi(tid + 256 * m)];
            }
        } else {
            // p=256: k = tid, j = tid; outputs land at tid + 256*q -> coalesced
            out[base + tid]                   = y0r * scale;
            out[base + tid + 256]             = y1r * scale;
            out[base + tid + 512]             = y2r * scale;
            out[base + tid + 768]             = y3r * scale;
            out[half_out + base + tid]        = y0i * scale;
            out[half_out + base + tid + 256]  = y1i * scale;
            out[half_out + base + tid + 512]  = y2i * scale;
            out[half_out + base + tid + 768]  = y3i * scale;
        }
    }
}

extern "C" void kernel_launch(void* const* d_in, const int* in_sizes, int n_in,
                              void* d_out, int out_size) {
    const float* re = (const float*)d_in[0];
    const float* im = (const float*)d_in[1];
    float* out = (float*)d_out;

    const int n_elems = in_sizes[0];                 // 8*4096*1024
    const int rows = n_elems / N_FFT;                // 32768
    const long long half = (long long)out_size / 2;  // re | im split

    ifft1024_r4_kernel<<<rows, THREADS>>>(re, im, out, half);
}

// round 7
// speedup vs baseline: 2.1333x; 1.3063x over previous
#include <cuda_runtime.h>

#define N_FFT   1024
#define THREADS 64
#define PAD(a)  ((a) + ((a) >> 4))
#define SMEM_F  (N_FFT + (N_FFT >> 4))   // 1088 floats per buffer

__device__ __forceinline__ void cmul(float& ar, float& ai, float br, float bi) {
    float tr = ar * br - ai * bi;
    ai = ar * bi + ai * br;
    ar = tr;
}

// In-place inverse radix-4 (sign +i): y0=a0+a2, y1=a1+i*a3, y2=a0-a2, y3=a1-i*a3
__device__ __forceinline__ void r4inv(float& u0r, float& u0i, float& u1r, float& u1i,
                                      float& u2r, float& u2i, float& u3r, float& u3i) {
    float a0r = u0r + u2r, a0i = u0i + u2i;
    float a1r = u0r - u2r, a1i = u0i - u2i;
    float a2r = u1r + u3r, a2i = u1i + u3i;
    float a3r = u1r - u3r, a3i = u1i - u3i;
    u0r = a0r + a2r; u0i = a0i + a2i;
    u1r = a1r - a3i; u1i = a1i + a3r;
    u2r = a0r - a2r; u2i = a0i - a2i;
    u3r = a1r + a3i; u3i = a1i - a3r;
}

// Inverse DFT-16 in registers via two radix-4 layers + W16 twiddles.
// Input: x[m] = t_m. Output: slot 4*q0+q1 holds y_{4*q1+q0}.
__device__ __forceinline__ void butterfly16(float* xr, float* xi) {
    #pragma unroll
    for (int m1 = 0; m1 < 4; ++m1)
        r4inv(xr[m1], xi[m1], xr[m1 + 4], xi[m1 + 4],
              xr[m1 + 8], xi[m1 + 8], xr[m1 + 12], xi[m1 + 12]);

    const float C1 = 0.92387953251128675613f;   // cos(pi/8)
    const float S1 = 0.38268343236508977173f;   // sin(pi/8)
    const float C2 = 0.70710678118654752440f;   // cos(pi/4)
    // slot m1+4*q0 *= W16^(m1*q0), W16 = exp(+i*pi/8)
    cmul(xr[5],  xi[5],   C1,  S1);   // W^1
    cmul(xr[6],  xi[6],   C2,  C2);   // W^2
    cmul(xr[7],  xi[7],   S1,  C1);   // W^3
    cmul(xr[9],  xi[9],   C2,  C2);   // W^2
    { float t = xr[10]; xr[10] = -xi[10]; xi[10] = t; }   // W^4 = i
    cmul(xr[11], xi[11], -C2,  C2);   // W^6
    cmul(xr[13], xi[13],  S1,  C1);   // W^3
    cmul(xr[14], xi[14], -C2,  C2);   // W^6
    cmul(xr[15], xi[15], -C1, -S1);   // W^9

    #pragma unroll
    for (int q0 = 0; q0 < 4; ++q0)
        r4inv(xr[4 * q0], xi[4 * q0], xr[4 * q0 + 1], xi[4 * q0 + 1],
              xr[4 * q0 + 2], xi[4 * q0 + 2], xr[4 * q0 + 3], xi[4 * q0 + 3]);
}

__global__ void __launch_bounds__(THREADS) ifft1024_r16_kernel(
    const float* __restrict__ re_in,
    const float* __restrict__ im_in,
    float* __restrict__ out,
    long long half_out)
{
    __shared__ float s0r[SMEM_F], s0i[SMEM_F];
    __shared__ float s1r[SMEM_F], s1i[SMEM_F];

    const int t = threadIdx.x;
    const long long base = (long long)blockIdx.x * N_FFT;
    const float TWO_PI = 6.28318530717958647692f;

    float xr[16], xi[16];

    // ── Pass 1: radix-16, p=1, k=0 (all external twiddles = 1) ──
    #pragma unroll
    for (int m = 0; m < 16; ++m) {
        xr[m] = re_in[base + t + 64 * m];   // coalesced
        xi[m] = im_in[base + t + 64 * m];
    }
    butterfly16(xr, xi);
    // write y_q at 16t+q; y_q lives in slot 4*(q&3)+(q>>2)
    #pragma unroll
    for (int q = 0; q < 16; ++q) {
        const int s = ((q & 3) << 2) + (q >> 2);
        s0r[PAD(16 * t + q)] = xr[s];
        s0i[PAD(16 * t + q)] = xi[s];
    }
    __syncthreads();

    // ── Pass 2: radix-16, p=16, k = t & 15 ──
    #pragma unroll
    for (int m = 0; m < 16; ++m) {
        xr[m] = s0r[PAD(t + 64 * m)];
        xi[m] = s0i[PAD(t + 64 * m)];
    }
    {
        const int k = t & 15;
        float c1, sn1;
        __sincosf(TWO_PI * (float)k * (1.0f / 256.0f), &sn1, &c1);
        float w1r = c1, w1i = sn1;
        float w2r = w1r, w2i = w1i; cmul(w2r, w2i, w1r, w1i);    // w^2
        float w3r = w2r, w3i = w2i; cmul(w3r, w3i, w1r, w1i);    // w^3
        float w4r = w2r, w4i = w2i; cmul(w4r, w4i, w2r, w2i);    // w^4
        float wgr = 1.0f, wgi = 0.0f;                            // w^(4g)
        #pragma unroll
        for (int g = 0; g < 4; ++g) {
            // u_{4g+m0} *= w^{m0} * w4^g
            cmul(xr[4 * g + 1], xi[4 * g + 1], w1r, w1i);
            cmul(xr[4 * g + 2], xi[4 * g + 2], w2r, w2i);
            cmul(xr[4 * g + 3], xi[4 * g + 3], w3r, w3i);
            if (g) {
                cmul(xr[4 * g],     xi[4 * g],     wgr, wgi);
                cmul(xr[4 * g + 1], xi[4 * g + 1], wgr, wgi);
                cmul(xr[4 * g + 2], xi[4 * g + 2], wgr, wgi);
                cmul(xr[4 * g + 3], xi[4 * g + 3], wgr, wgi);
            }
            if (g < 3) cmul(wgr, wgi, w4r, w4i);
        }
    }
    butterfly16(xr, xi);
    {
        const int j = ((t & ~15) << 4) + (t & 15);   // 256*(t>>4) + k
        #pragma unroll
        for (int q = 0; q < 16; ++q) {
            const int s = ((q & 3) << 2) + (q >> 2);
            s1r[PAD(j + 16 * q)] = xr[s];
            s1i[PAD(j + 16 * q)] = xi[s];
        }
    }
    __syncthreads();

    // ── Pass 3: radix-4, p=256, gid = t + 64*sdx, direct store to gmem ──
    const float scale = 1.0f / (float)N_FFT;
    #pragma unroll
    for (int sdx = 0; sdx < 4; ++sdx) {
        const int gid = t + 64 * sdx;
        float u0r = s1r[PAD(gid)],       u0i = s1i[PAD(gid)];
        float u1r = s1r[PAD(gid + 256)], u1i = s1i[PAD(gid + 256)];
        float u2r = s1r[PAD(gid + 512)], u2i = s1i[PAD(gid + 512)];
        float u3r = s1r[PAD(gid + 768)], u3i = s1i[PAD(gid + 768)];

        float c1, sn1;
        __sincosf(TWO_PI * (float)gid * (1.0f / 1024.0f), &sn1, &c1);
        float w2r = c1, w2i = sn1;  cmul(w2r, w2i, c1, sn1);   // w^2
        float w3r = w2r, w3i = w2i; cmul(w3r, w3i, c1, sn1);   // w^3
        cmul(u1r, u1i, c1, sn1);
        cmul(u2r, u2i, w2r, w2i);
        cmul(u3r, u3i, w3r, w3i);
        r4inv(u0r, u0i, u1r, u1i, u2r, u2i, u3r, u3i);

        out[base + gid]                  = u0r * scale;
        out[base + gid + 256]            = u1r * scale;
        out[base + gid + 512]            = u2r * scale;
        out[base + gid + 768]            = u3r * scale;
        out[half_out + base + gid]       = u0i * scale;
        out[half_out + base + gid + 256] = u1i * scale;
        out[half_out + base + gid + 512] = u2i * scale;
        out[half_out + base + gid + 768] = u3i * scale;
    }
}

extern "C" void kernel_launch(void* const* d_in, const int* in_sizes, int n_in,
                              void* d_out, int out_size) {
    const float* re = (const float*)d_in[0];
    const float* im = (const float*)d_in[1];
    float* out = (float*)d_out;

    const int n_elems = in_sizes[0];                 // 8*4096*1024
    const int rows = n_elems / N_FFT;                // 32768
    const long long half = (long long)out_size / 2;  // re | im split

    ifft1024_r16_kernel<<<rows, THREADS>>>(re, im, out, half);
}

// round 11
// speedup vs baseline: 2.1726x; 1.0184x over previous
#include <cuda_runtime.h>

#define N_FFT   1024
#define THREADS 64                      // 2 warps = 2 rows per CTA
#define ROWPAD(a) ((a) + ((a) >> 5))    // float2 padding, conflict-free
#define SMEM_F2   (N_FFT + (N_FFT >> 5))  // 1056 float2 per row

__device__ __forceinline__ void cmul(float& ar, float& ai, float br, float bi) {
    float tr = ar * br - ai * bi;
    ai = ar * bi + ai * br;
    ar = tr;
}

// In-place inverse radix-4 (sign +i): y0=a0+a2, y1=a1+i*a3, y2=a0-a2, y3=a1-i*a3
__device__ __forceinline__ void r4inv(float& u0r, float& u0i, float& u1r, float& u1i,
                                      float& u2r, float& u2i, float& u3r, float& u3i) {
    float a0r = u0r + u2r, a0i = u0i + u2i;
    float a1r = u0r - u2r, a1i = u0i - u2i;
    float a2r = u1r + u3r, a2i = u1i + u3i;
    float a3r = u1r - u3r, a3i = u1i - u3i;
    u0r = a0r + a2r; u0i = a0i + a2i;
    u1r = a1r - a3i; u1i = a1i + a3r;
    u2r = a0r - a2r; u2i = a0i - a2i;
    u3r = a1r + a3i; u3i = a1i - a3r;
}

// cos/sin(pi*k/16) for k = 0..21  (W32^k, W32 = exp(+i*pi/16))
__constant__ float W32R[22] = {
    1.0f,  0.98078528040323044913f,  0.92387953251128675613f,  0.83146961230254523708f,
    0.70710678118654752440f,  0.55557023301960222474f,  0.38268343236508977173f,
    0.19509032201612826785f,  0.0f, -0.19509032201612826785f, -0.38268343236508977173f,
   -0.55557023301960222474f, -0.70710678118654752440f, -0.83146961230254523708f,
   -0.92387953251128675613f, -0.98078528040323044913f, -1.0f, -0.98078528040323044913f,
   -0.92387953251128675613f, -0.83146961230254523708f, -0.70710678118654752440f,
   -0.55557023301960222474f };
__constant__ float W32I[22] = {
    0.0f,  0.19509032201612826785f,  0.38268343236508977173f,  0.55557023301960222474f,
    0.70710678118654752440f,  0.83146961230254523708f,  0.92387953251128675613f,
    0.98078528040323044913f,  1.0f,  0.98078528040323044913f,  0.92387953251128675613f,
    0.83146961230254523708f,  0.70710678118654752440f,  0.55557023301960222474f,
    0.38268343236508977173f,  0.19509032201612826785f,  0.0f, -0.19509032201612826785f,
   -0.38268343236508977173f, -0.55557023301960222474f, -0.70710678118654752440f,
   -0.83146961230254523708f };

// Inverse DFT-8 in-place on 8 consecutive slots: output y_q at slot q.
// NOTE: combine stage snapshots E/O into locals first — the in-place loop
// version has a RAW hazard (write b[q+4] clobbers E_{q+2} before its read).
__device__ __forceinline__ void dft8inv(float* br, float* bi) {
    const float C = 0.70710678118654752440f;
    r4inv(br[0], bi[0], br[2], bi[2], br[4], bi[4], br[6], bi[6]);  // E_q -> slot 2q
    r4inv(br[1], bi[1], br[3], bi[3], br[5], bi[5], br[7], bi[7]);  // O_q -> slot 2q+1
    cmul(br[3], bi[3],  C, C);                                      // O1 *= W8^1
    { float t = br[5]; br[5] = -bi[5]; bi[5] = t; }                 // O2 *= i
    cmul(br[7], bi[7], -C, C);                                      // O3 *= W8^3

    const float e0r = br[0], e0i = bi[0], e1r = br[2], e1i = bi[2];
    const float e2r = br[4], e2i = bi[4], e3r = br[6], e3i = bi[6];
    const float o0r = br[1], o0i = bi[1], o1r = br[3], o1i = bi[3];
    const float o2r = br[5], o2i = bi[5], o3r = br[7], o3i = bi[7];

    br[0] = e0r + o0r;  bi[0] = e0i + o0i;
    br[1] = e1r + o1r;  bi[1] = e1i + o1i;
    br[2] = e2r + o2r;  bi[2] = e2i + o2i;
    br[3] = e3r + o3r;  bi[3] = e3i + o3i;
    br[4] = e0r - o0r;  bi[4] = e0i - o0i;
    br[5] = e1r - o1r;  bi[5] = e1i - o1i;
    br[6] = e2r - o2r;  bi[6] = e2i - o2i;
    br[7] = e3r - o3r;  bi[7] = e3i - o3i;
}

// Inverse DFT-32 in registers. Output: slot 8*(q&3) + (q>>2) holds y_q.
__device__ __forceinline__ void butterfly32(float* xr, float* xi) {
    // Layer 1: 8 radix-4 DFTs (stride 8): y_{q1} -> slot m2 + 8*q1
    #pragma unroll
    for (int m2 = 0; m2 < 8; ++m2)
        r4inv(xr[m2], xi[m2], xr[m2 + 8], xi[m2 + 8],
              xr[m2 + 16], xi[m2 + 16], xr[m2 + 24], xi[m2 + 24]);
    // Twiddle: slot m2 + 8*q1 *= W32^(q1*m2)
    #pragma unroll
    for (int q1 = 1; q1 < 4; ++q1)
        #pragma unroll
        for (int m2 = 1; m2 < 8; ++m2)
            cmul(xr[m2 + 8 * q1], xi[m2 + 8 * q1], W32R[q1 * m2], W32I[q1 * m2]);
    // Layer 2: 4 DFT-8s over consecutive slots: slot 8q1+q2 = y_{q1+4q2}
    #pragma unroll
    for (int q1 = 0; q1 < 4; ++q1)
        dft8inv(xr + 8 * q1, xi + 8 * q1);
}

__global__ void __launch_bounds__(THREADS) ifft1024_r32_kernel(
    const float* __restrict__ re_in,
    const float* __restrict__ im_in,
    float* __restrict__ out,
    long long half_out)
{
    __shared__ float2 sbuf[2][SMEM_F2];

    const int t   = threadIdx.x & 31;        // lane = position within row
    const int wid = threadIdx.x >> 5;        // warp = row within CTA
    const long long row  = (long long)blockIdx.x * 2 + wid;
    const long long base = row * N_FFT;
    const float TWO_PI = 6.28318530717958647692f;

    float xr[32], xi[32];

    // ── Pass 1: radix-32, p=1 (no external twiddles). Coalesced 128B loads. ──
    #pragma unroll
    for (int m = 0; m < 32; ++m) {
        xr[m] = re_in[base + t + 32 * m];
        xi[m] = im_in[base + t + 32 * m];
    }
    butterfly32(xr, xi);

    // Write y_q to position 32t + q (warp-private region, conflict-free)
    #pragma unroll
    for (int q = 0; q < 32; ++q) {
        const int s = ((q & 3) << 3) + (q >> 2);
        sbuf[wid][ROWPAD(32 * t + q)] = make_float2(xr[s], xi[s]);
    }
    __syncwarp();

    // ── Pass 2: radix-32, p=32, k=t. Read legs at position t + 32m. ──
    #pragma unroll
    for (int m = 0; m < 32; ++m) {
        float2 v = sbuf[wid][t + 33 * m];    // ROWPAD(t + 32m) = t + 33m
        xr[m] = v.x;
        xi[m] = v.y;
    }
    // Twiddle u_m *= w^m, w = exp(+2*pi*i * t / 1024); chain re-anchored every 8.
    {
        const float ang = TWO_PI * (float)t * (1.0f / 1024.0f);
        float w1r, w1i;
        __sincosf(ang, &w1i, &w1r);
        #pragma unroll
        for (int j = 0; j < 4; ++j) {
            float cr, ci;
            if (j == 0) { cr = 1.0f; ci = 0.0f; }
            else        { __sincosf(ang * (float)(8 * j), &ci, &cr); }
            #pragma unroll
            for (int r = 0; r < 8; ++r) {
                const int m = 8 * j + r;
                if (m > 0) cmul(xr[m], xi[m], cr, ci);
                cmul(cr, ci, w1r, w1i);
            }
        }
    }
    butterfly32(xr, xi);

    // ── Store: y_q at natural position t + 32q; coalesced 128B stores. ──
    const float scale = 1.0f / (float)N_FFT;
    #pragma unroll
    for (int q = 0; q < 32; ++q) {
        const int s = ((q & 3) << 3) + (q >> 2);
        out[base + t + 32 * q]            = xr[s] * scale;
        out[half_out + base + t + 32 * q] = xi[s] * scale;
    }
}

extern "C" void kernel_launch(void* const* d_in, const int* in_sizes, int n_in,
                              void* d_out, int out_size) {
    const float* re = (const float*)d_in[0];
    const float* im = (const float*)d_in[1];
    float* out = (float*)d_out;

    const int n_elems = in_sizes[0];                 // 8*4096*1024
    const int rows = n_elems / N_FFT;                // 32768
    const long long half = (long long)out_size / 2;  // re | im split

    ifft1024_r32_kernel<<<rows / 2, THREADS>>>(re, im, out, half);
}

// round 12
// speedup vs baseline: 2.1874x; 1.0068x over previous
#include <cuda_runtime.h>

typedef unsigned long long u64;

#define N_FFT   1024
#define THREADS 64                        // 2 warps = 2 rows per CTA
#define ROWPAD(a) ((a) + ((a) >> 5))      // 64-bit padding, conflict-free
#define SMEM_C    (N_FFT + (N_FFT >> 5))  // 1056 packed complex per row

// ── packed complex primitives: p = (re in lo, im in hi) ──────────────────
__device__ __forceinline__ u64 cpack(float r, float i) {
    u64 p; asm("mov.b64 %0,{%1,%2};" : "=l"(p) : "f"(r), "f"(i)); return p;
}
__device__ __forceinline__ void cunpack(u64 p, float& r, float& i) {
    asm("mov.b64 {%0,%1},%2;" : "=f"(r), "=f"(i) : "l"(p));
}
__device__ __forceinline__ u64 cadd(u64 a, u64 b) {
    u64 o; asm("add.rn.f32x2 %0,%1,%2;" : "=l"(o) : "l"(a), "l"(b)); return o;
}
__device__ __forceinline__ u64 cmul2(u64 a, u64 b) {
    u64 o; asm("mul.rn.f32x2 %0,%1,%2;" : "=l"(o) : "l"(a), "l"(b)); return o;
}
__device__ __forceinline__ u64 cfma(u64 a, u64 b, u64 c) {
    u64 o; asm("fma.rn.f32x2 %0,%1,%2,%3;" : "=l"(o) : "l"(a), "l"(b), "l"(c)); return o;
}
// a - b  ==  fma(b, (-1,-1), a)   (avoids relying on sub.f32x2)
__device__ __forceinline__ u64 csub(u64 a, u64 b, u64 n1) { return cfma(b, n1, a); }
__device__ __forceinline__ u64 cswap(u64 a) {              // (re,im) -> (im,re)
    float r, i; cunpack(a, r, i); return cpack(i, r);
}
// multiply by +i: (re,im) -> (-im, re) = swap then flip sign of low word
__device__ __forceinline__ u64 imul(u64 a) { return cswap(a) ^ 0x80000000ULL; }
// a * (c + i s) with t1=(c,c), t2=(-s,s)
__device__ __forceinline__ u64 cmulw(u64 a, u64 t1, u64 t2) {
    return cfma(cswap(a), t2, cmul2(a, t1));
}

// ── W32 twiddle tables: W32^k = cos(pi k/16) + i sin(pi k/16), k=0..21 ──
// T1[k]={c,c}, T2[k]={-s,s}
__constant__ float2 W32T1[22] = {
    { 1.0f, 1.0f},
    { 0.98078528040323044913f,  0.98078528040323044913f},
    { 0.92387953251128675613f,  0.92387953251128675613f},
    { 0.83146961230254523708f,  0.83146961230254523708f},
    { 0.70710678118654752440f,  0.70710678118654752440f},
    { 0.55557023301960222474f,  0.55557023301960222474f},
    { 0.38268343236508977173f,  0.38268343236508977173f},
    { 0.19509032201612826785f,  0.19509032201612826785f},
    { 0.0f, 0.0f},
    {-0.19509032201612826785f, -0.19509032201612826785f},
    {-0.38268343236508977173f, -0.38268343236508977173f},
    {-0.55557023301960222474f, -0.55557023301960222474f},
    {-0.70710678118654752440f, -0.70710678118654752440f},
    {-0.83146961230254523708f, -0.83146961230254523708f},
    {-0.92387953251128675613f, -0.92387953251128675613f},
    {-0.98078528040323044913f, -0.98078528040323044913f},
    {-1.0f, -1.0f},
    {-0.98078528040323044913f, -0.98078528040323044913f},
    {-0.92387953251128675613f, -0.92387953251128675613f},
    {-0.83146961230254523708f, -0.83146961230254523708f},
    {-0.70710678118654752440f, -0.70710678118654752440f},
    {-0.55557023301960222474f, -0.55557023301960222474f} };
__constant__ float2 W32T2[22] = {
    { 0.0f, 0.0f},
    {-0.19509032201612826785f,  0.19509032201612826785f},
    {-0.38268343236508977173f,  0.38268343236508977173f},
    {-0.55557023301960222474f,  0.55557023301960222474f},
    {-0.70710678118654752440f,  0.70710678118654752440f},
    {-0.83146961230254523708f,  0.83146961230254523708f},
    {-0.92387953251128675613f,  0.92387953251128675613f},
    {-0.98078528040323044913f,  0.98078528040323044913f},
    {-1.0f, 1.0f},
    {-0.98078528040323044913f,  0.98078528040323044913f},
    {-0.92387953251128675613f,  0.92387953251128675613f},
    {-0.83146961230254523708f,  0.83146961230254523708f},
    {-0.70710678118654752440f,  0.70710678118654752440f},
    {-0.55557023301960222474f,  0.55557023301960222474f},
    {-0.38268343236508977173f,  0.38268343236508977173f},
    {-0.19509032201612826785f,  0.19509032201612826785f},
    { 0.0f, 0.0f},
    { 0.19509032201612826785f, -0.19509032201612826785f},
    { 0.38268343236508977173f, -0.38268343236508977173f},
    { 0.55557023301960222474f, -0.55557023301960222474f},
    { 0.70710678118654752440f, -0.70710678118654752440f},
    { 0.83146961230254523708f, -0.83146961230254523708f} };

// Inverse radix-4 in packed regs (sign +i). Writes back in natural order.
__device__ __forceinline__ void r4inv(u64& u0, u64& u1, u64& u2, u64& u3, u64 n1) {
    u64 a0 = cadd(u0, u2), a1 = csub(u0, u2, n1);
    u64 a2 = cadd(u1, u3), a3 = csub(u1, u3, n1);
    u0 = cadd(a0, a2);
    u2 = csub(a0, a2, n1);
    u64 d = imul(a3);
    u1 = cadd(a1, d);
    u3 = csub(a1, d, n1);
}

// Inverse DFT-8 in-place on 8 consecutive slots; output y_q at slot q.
// c7t1/c7t2 = packed (C,C)/(-C,C);  c7t1n = (-C,-C) for W8^3 = -C+iC.
__device__ __forceinline__ void dft8inv(u64* b, u64 n1, u64 c7t1, u64 c7t2, u64 c7t1n) {
    r4inv(b[0], b[2], b[4], b[6], n1);   // E_q -> slot 2q
    r4inv(b[1], b[3], b[5], b[7], n1);   // O_q -> slot 2q+1
    b[3] = cmulw(b[3], c7t1,  c7t2);     // O1 *= W8   ( C+iC)
    b[5] = imul(b[5]);                   // O2 *= i
    b[7] = cmulw(b[7], c7t1n, c7t2);     // O3 *= W8^3 (-C+iC)
    const u64 e0 = b[0], e1 = b[2], e2 = b[4], e3 = b[6];
    const u64 o0 = b[1], o1 = b[3], o2 = b[5], o3 = b[7];
    b[0] = cadd(e0, o0);  b[1] = cadd(e1, o1);
    b[2] = cadd(e2, o2);  b[3] = cadd(e3, o3);
    b[4] = csub(e0, o0, n1);  b[5] = csub(e1, o1, n1);
    b[6] = csub(e2, o2, n1);  b[7] = csub(e3, o3, n1);
}

// Inverse DFT-32 in registers. Output: slot 8*(q&3) + (q>>2) holds y_q.
__device__ __forceinline__ void butterfly32(u64* x, u64 n1) {
    #pragma unroll
    for (int m2 = 0; m2 < 8; ++m2)
        r4inv(x[m2], x[m2 + 8], x[m2 + 16], x[m2 + 24], n1);
    #pragma unroll
    for (int q1 = 1; q1 < 4; ++q1)
        #pragma unroll
        for (int m2 = 1; m2 < 8; ++m2) {
            const float2 t1 = W32T1[q1 * m2];
            const float2 t2 = W32T2[q1 * m2];
            x[m2 + 8 * q1] = cmulw(x[m2 + 8 * q1],
                                   cpack(t1.x, t1.y), cpack(t2.x, t2.y));
        }
    const float C = 0.70710678118654752440f;
    const u64 c7t1  = cpack( C,  C);
    const u64 c7t2  = cpack(-C,  C);
    const u64 c7t1n = cpack(-C, -C);
    #pragma unroll
    for (int q1 = 0; q1 < 4; ++q1)
        dft8inv(x + 8 * q1, n1, c7t1, c7t2, c7t1n);
}

__global__ void __launch_bounds__(THREADS) ifft1024_r32p_kernel(
    const float* __restrict__ re_in,
    const float* __restrict__ im_in,
    float* __restrict__ out,
    long long half_out)
{
    __shared__ u64 sbuf[2][SMEM_C];

    const int t   = threadIdx.x & 31;        // lane = position within row
    const int wid = threadIdx.x >> 5;        // warp = row within CTA
    const long long row  = (long long)blockIdx.x * 2 + wid;
    const long long base = row * N_FFT;
    const float TWO_PI = 6.28318530717958647692f;
    const u64 n1 = cpack(-1.0f, -1.0f);

    u64 x[32];

    // ── Pass 1: radix-32, p=1 (no external twiddles). Coalesced loads. ──
    #pragma unroll
    for (int m = 0; m < 32; ++m)
        x[m] = cpack(re_in[base + t + 32 * m], im_in[base + t + 32 * m]);
    butterfly32(x, n1);

    // Write y_q to position 32t + q (warp-private region, conflict-free)
    #pragma unroll
    for (int q = 0; q < 32; ++q) {
        const int s = ((q & 3) << 3) + (q >> 2);
        sbuf[wid][ROWPAD(32 * t + q)] = x[s];
    }
    __syncwarp();

    // ── Pass 2: radix-32, p=32, k=t. Read legs at position t + 32m. ──
    #pragma unroll
    for (int m = 0; m < 32; ++m)
        x[m] = sbuf[wid][t + 33 * m];        // ROWPAD(t + 32m) = t + 33m

    // Twiddle u_m *= w^m, w = exp(+2*pi*i * t/1024); chain re-anchored every 8.
    {
        const float ang = TWO_PI * (float)t * (1.0f / 1024.0f);
        float c1, s1;
        __sincosf(ang, &s1, &c1);
        const u64 w1t1 = cpack(c1, c1);
        const u64 w1t2 = cpack(-s1, s1);
        #pragma unroll
        for (int j = 0; j < 4; ++j) {
            float cr, ci;
            if (j == 0) { cr = 1.0f; ci = 0.0f; }
            else        { __sincosf(ang * (float)(8 * j), &ci, &cr); }
            u64 ch = cpack(cr, ci);
            #pragma unroll
            for (int r = 0; r < 8; ++r) {
                const int m = 8 * j + r;
                if (m > 0) {
                    float hr, hi;
                    cunpack(ch, hr, hi);
                    x[m] = cmulw(x[m], cpack(hr, hr), cpack(-hi, hi));
                }
                ch = cmulw(ch, w1t1, w1t2);
            }
        }
    }
    butterfly32(x, n1);

    // ── Store: y_q at natural position t + 32q; coalesced stores. ──
    const float scale = 1.0f / (float)N_FFT;
    const u64 ks = cpack(scale, scale);
    #pragma unroll
    for (int q = 0; q < 32; ++q) {
        const int s = ((q & 3) << 3) + (q >> 2);
        float vr, vi;
        cunpack(cmul2(x[s], ks), vr, vi);
        out[base + t + 32 * q]            = vr;
        out[half_out + base + t + 32 * q] = vi;
    }
}

extern "C" void kernel_launch(void* const* d_in, const int* in_sizes, int n_in,
                              void* d_out, int out_size) {
    const float* re = (const float*)d_in[0];
    const float* im = (const float*)d_in[1];
    float* out = (float*)d_out;

    const int n_elems = in_sizes[0];                 // 8*4096*1024
    const int rows = n_elems / N_FFT;                // 32768
    const long long half = (long long)out_size / 2;  // re | im split

    ifft1024_r32p_kernel<<<rows / 2, THREADS>>>(re, im, out, half);
}

// round 13
// speedup vs baseline: 2.4390x; 1.1150x over previous
#include <cuda_runtime.h>

typedef unsigned long long u64;

#define N_FFT   1024
#define THREADS 64                        // 2 warps = 2 rows in flight per CTA
#define ROWS_PER_WARP 4
#define ROWPAD(a) ((a) + ((a) >> 5))      // 64-bit padding, conflict-free
#define SMEM_C    (N_FFT + (N_FFT >> 5))  // 1056 packed complex per row

// ── packed complex primitives: p = (re in lo, im in hi) ──────────────────
__device__ __forceinline__ u64 cpack(float r, float i) {
    u64 p; asm("mov.b64 %0,{%1,%2};" : "=l"(p) : "f"(r), "f"(i)); return p;
}
__device__ __forceinline__ void cunpack(u64 p, float& r, float& i) {
    asm("mov.b64 {%0,%1},%2;" : "=f"(r), "=f"(i) : "l"(p));
}
__device__ __forceinline__ u64 cadd(u64 a, u64 b) {
    u64 o; asm("add.rn.f32x2 %0,%1,%2;" : "=l"(o) : "l"(a), "l"(b)); return o;
}
__device__ __forceinline__ u64 cmul2(u64 a, u64 b) {
    u64 o; asm("mul.rn.f32x2 %0,%1,%2;" : "=l"(o) : "l"(a), "l"(b)); return o;
}
__device__ __forceinline__ u64 cfma(u64 a, u64 b, u64 c) {
    u64 o; asm("fma.rn.f32x2 %0,%1,%2,%3;" : "=l"(o) : "l"(a), "l"(b), "l"(c)); return o;
}
// a - b  ==  fma(b, (-1,-1), a)
__device__ __forceinline__ u64 csub(u64 a, u64 b, u64 n1) { return cfma(b, n1, a); }
__device__ __forceinline__ u64 cswap(u64 a) {              // (re,im) -> (im,re)
    float r, i; cunpack(a, r, i); return cpack(i, r);
}
// multiply by +i: (re,im) -> (-im, re)
__device__ __forceinline__ u64 imul(u64 a) { return cswap(a) ^ 0x80000000ULL; }
// a * (c + i s) with t1=(c,c), t2=(-s,s)
__device__ __forceinline__ u64 cmulw(u64 a, u64 t1, u64 t2) {
    return cfma(cswap(a), t2, cmul2(a, t1));
}

// ── W32 twiddle tables: W32^k = cos(pi k/16) + i sin(pi k/16), k=0..21 ──
__constant__ float2 W32T1[22] = {
    { 1.0f, 1.0f},
    { 0.98078528040323044913f,  0.98078528040323044913f},
    { 0.92387953251128675613f,  0.92387953251128675613f},
    { 0.83146961230254523708f,  0.83146961230254523708f},
    { 0.70710678118654752440f,  0.70710678118654752440f},
    { 0.55557023301960222474f,  0.55557023301960222474f},
    { 0.38268343236508977173f,  0.38268343236508977173f},
    { 0.19509032201612826785f,  0.19509032201612826785f},
    { 0.0f, 0.0f},
    {-0.19509032201612826785f, -0.19509032201612826785f},
    {-0.38268343236508977173f, -0.38268343236508977173f},
    {-0.55557023301960222474f, -0.55557023301960222474f},
    {-0.70710678118654752440f, -0.70710678118654752440f},
    {-0.83146961230254523708f, -0.83146961230254523708f},
    {-0.92387953251128675613f, -0.92387953251128675613f},
    {-0.98078528040323044913f, -0.98078528040323044913f},
    {-1.0f, -1.0f},
    {-0.98078528040323044913f, -0.98078528040323044913f},
    {-0.92387953251128675613f, -0.92387953251128675613f},
    {-0.83146961230254523708f, -0.83146961230254523708f},
    {-0.70710678118654752440f, -0.70710678118654752440f},
    {-0.55557023301960222474f, -0.55557023301960222474f} };
__constant__ float2 W32T2[22] = {
    { 0.0f, 0.0f},
    {-0.19509032201612826785f,  0.19509032201612826785f},
    {-0.38268343236508977173f,  0.38268343236508977173f},
    {-0.55557023301960222474f,  0.55557023301960222474f},
    {-0.70710678118654752440f,  0.70710678118654752440f},
    {-0.83146961230254523708f,  0.83146961230254523708f},
    {-0.92387953251128675613f,  0.92387953251128675613f},
    {-0.98078528040323044913f,  0.98078528040323044913f},
    {-1.0f, 1.0f},
    {-0.98078528040323044913f,  0.98078528040323044913f},
    {-0.92387953251128675613f,  0.92387953251128675613f},
    {-0.83146961230254523708f,  0.83146961230254523708f},
    {-0.70710678118654752440f,  0.70710678118654752440f},
    {-0.55557023301960222474f,  0.55557023301960222474f},
    {-0.38268343236508977173f,  0.38268343236508977173f},
    {-0.19509032201612826785f,  0.19509032201612826785f},
    { 0.0f, 0.0f},
    { 0.19509032201612826785f, -0.19509032201612826785f},
    { 0.38268343236508977173f, -0.38268343236508977173f},
    { 0.55557023301960222474f, -0.55557023301960222474f},
    { 0.70710678118654752440f, -0.70710678118654752440f},
    { 0.83146961230254523708f, -0.83146961230254523708f} };

// Inverse radix-4 in packed regs (sign +i).
__device__ __forceinline__ void r4inv(u64& u0, u64& u1, u64& u2, u64& u3, u64 n1) {
    u64 a0 = cadd(u0, u2), a1 = csub(u0, u2, n1);
    u64 a2 = cadd(u1, u3), a3 = csub(u1, u3, n1);
    u0 = cadd(a0, a2);
    u2 = csub(a0, a2, n1);
    u64 d = imul(a3);
    u1 = cadd(a1, d);
    u3 = csub(a1, d, n1);
}

// Inverse DFT-8 in-place on 8 consecutive slots; output y_q at slot q.
__device__ __forceinline__ void dft8inv(u64* b, u64 n1, u64 c7t1, u64 c7t2, u64 c7t1n) {
    r4inv(b[0], b[2], b[4], b[6], n1);   // E_q -> slot 2q
    r4inv(b[1], b[3], b[5], b[7], n1);   // O_q -> slot 2q+1
    b[3] = cmulw(b[3], c7t1,  c7t2);     // O1 *= W8   ( C+iC)
    b[5] = imul(b[5]);                   // O2 *= i
    b[7] = cmulw(b[7], c7t1n, c7t2);     // O3 *= W8^3 (-C+iC)
    const u64 e0 = b[0], e1 = b[2], e2 = b[4], e3 = b[6];
    const u64 o0 = b[1], o1 = b[3], o2 = b[5], o3 = b[7];
    b[0] = cadd(e0, o0);  b[1] = cadd(e1, o1);
    b[2] = cadd(e2, o2);  b[3] = cadd(e3, o3);
    b[4] = csub(e0, o0, n1);  b[5] = csub(e1, o1, n1);
    b[6] = csub(e2, o2, n1);  b[7] = csub(e3, o3, n1);
}

// Inverse DFT-32 in registers. Output: slot 8*(q&3) + (q>>2) holds y_q.
__device__ __forceinline__ void butterfly32(u64* x, u64 n1) {
    #pragma unroll
    for (int m2 = 0; m2 < 8; ++m2)
        r4inv(x[m2], x[m2 + 8], x[m2 + 16], x[m2 + 24], n1);
    #pragma unroll
    for (int q1 = 1; q1 < 4; ++q1)
        #pragma unroll
        for (int m2 = 1; m2 < 8; ++m2) {
            const float2 t1 = W32T1[q1 * m2];
            const float2 t2 = W32T2[q1 * m2];
            x[m2 + 8 * q1] = cmulw(x[m2 + 8 * q1],
                                   cpack(t1.x, t1.y), cpack(t2.x, t2.y));
        }
    const float C = 0.70710678118654752440f;
    const u64 c7t1  = cpack( C,  C);
    const u64 c7t2  = cpack(-C,  C);
    const u64 c7t1n = cpack(-C, -C);
    #pragma unroll
    for (int q1 = 0; q1 < 4; ++q1)
        dft8inv(x + 8 * q1, n1, c7t1, c7t2, c7t1n);
}

__global__ void __launch_bounds__(THREADS) ifft1024_r32pp_kernel(
    const float* __restrict__ re_in,
    const float* __restrict__ im_in,
    float* __restrict__ out,
    long long half_out)
{
    __shared__ u64 sbuf[2][SMEM_C];

    const int t   = threadIdx.x & 31;         // lane = position within row
    const int wid = threadIdx.x >> 5;         // warp = row within CTA
    const int warp_gid = blockIdx.x * 2 + wid;
    const int W = gridDim.x * 2;              // total warps = rows per iteration
    const float TWO_PI = 6.28318530717958647692f;
    const u64 n1 = cpack(-1.0f, -1.0f);

    for (int it = 0; it < ROWS_PER_WARP; ++it) {
        const long long row  = (long long)warp_gid + (long long)it * W;
        const long long base = row * N_FFT;

        u64 x[32];

        // ── Pass 1 loads: coalesced, streaming (read-once). ──
        #pragma unroll
        for (int m = 0; m < 32; ++m)
            x[m] = cpack(__ldcs(re_in + base + t + 32 * m),
                         __ldcs(im_in + base + t + 32 * m));

        // ── Prefetch next row into L2 while this row computes. ──
        if (it + 1 < ROWS_PER_WARP) {
            const long long nbase = base + (long long)W * N_FFT;
            asm volatile("prefetch.global.L2 [%0];" ::
                         "l"(re_in + nbase + 32 * t));   // lane t: line t (128B)
            asm volatile("prefetch.global.L2 [%0];" ::
                         "l"(im_in + nbase + 32 * t));
        }

        butterfly32(x, n1);

        // Write y_q to position 32t + q (warp-private region, conflict-free)
        #pragma unroll
        for (int q = 0; q < 32; ++q) {
            const int s = ((q & 3) << 3) + (q >> 2);
            sbuf[wid][ROWPAD(32 * t + q)] = x[s];
        }
        __syncwarp();

        // ── Pass 2: radix-32, p=32, k=t. Read legs at position t + 32m. ──
        #pragma unroll
        for (int m = 0; m < 32; ++m)
            x[m] = sbuf[wid][t + 33 * m];     // ROWPAD(t + 32m) = t + 33m
        __syncwarp();                         // reads done before next iter's writes

        // Twiddle u_m *= w^m, w = exp(+2*pi*i*t/1024); chain re-anchored every 8.
        {
            const float ang = TWO_PI * (float)t * (1.0f / 1024.0f);
            float c1, s1;
            __sincosf(ang, &s1, &c1);
            const u64 w1t1 = cpack(c1, c1);
            const u64 w1t2 = cpack(-s1, s1);
            #pragma unroll
            for (int j = 0; j < 4; ++j) {
                float cr, ci;
                if (j == 0) { cr = 1.0f; ci = 0.0f; }
                else        { __sincosf(ang * (float)(8 * j), &ci, &cr); }
                u64 ch = cpack(cr, ci);
                #pragma unroll
                for (int r = 0; r < 8; ++r) {
                    const int m = 8 * j + r;
                    if (m > 0) {
                        float hr, hi;
                        cunpack(ch, hr, hi);
                        x[m] = cmulw(x[m], cpack(hr, hr), cpack(-hi, hi));
                    }
                    ch = cmulw(ch, w1t1, w1t2);
                }
            }
        }
        butterfly32(x, n1);

        // ── Store: y_q at natural position t + 32q; coalesced streaming stores. ──
        const float scale = 1.0f / (float)N_FFT;
        const u64 ks = cpack(scale, scale);
        #pragma unroll
        for (int q = 0; q < 32; ++q) {
            const int s = ((q & 3) << 3) + (q >> 2);
            float vr, vi;
            cunpack(cmul2(x[s], ks), vr, vi);
            __stcs(out + base + t + 32 * q, vr);
            __stcs(out + half_out + base + t + 32 * q, vi);
        }
    }
}

extern "C" void kernel_launch(void* const* d_in, const int* in_sizes, int n_in,
                              void* d_out, int out_size) {
    const float* re = (const float*)d_in[0];
    const float* im = (const float*)d_in[1];
    float* out = (float*)d_out;

    const int n_elems = in_sizes[0];                 // 8*4096*1024
    const int rows = n_elems / N_FFT;                // 32768
    const long long half = (long long)out_size / 2;  // re | im split

    const int total_warps = rows / ROWS_PER_WARP;    // 8192
    const int blocks = total_warps / 2;              // 4096 CTAs of 2 warps

    ifft1024_r32pp_kernel<<<blocks, THREADS>>>(re, im, out, half);
}